// round 1
// baseline (speedup 1.0000x reference)
#include <cuda_runtime.h>

// CIF: continuous integrate-and-fire.
// Shapes fixed by the problem: hidden [B,T,H] f32, alphas [B,T] f32,
// target_lengths [B] i32 -> out [B,L,H] f32.
#define BB 32
#define TT 2000
#define HH 512
#define LL 256
#define THRESH 0.95f

// Scratch (no device allocation allowed -> __device__ globals).
__device__ int   g_fire[BB * LL];   // fire time per token
__device__ float g_cur [BB * LL];   // weight of the firing frame for this token
__device__ float g_rem [BB * LL];   // leftover weight of firing frame -> next token
__device__ float g_scale[BB];       // per-batch alpha rescale factor
__device__ int   g_ntok[BB];        // number of emitted tokens (<= LL)

// ---------------------------------------------------------------------------
// Kernel 1: per-batch alpha sum + exact sequential fire scan.
// One CTA per batch. The scan itself is a single-thread replay of the
// reference recurrence so that fire decisions match the reference's
// data-dependent control flow.
// ---------------------------------------------------------------------------
__global__ void cif_scan_kernel(const float* __restrict__ alphas,
                                const int*   __restrict__ tlen)
{
    const int b = blockIdx.x;
    __shared__ float  sa[TT];
    __shared__ double red[256];

    const float* ab = alphas + (size_t)b * TT;

    // Stage alphas into smem and accumulate partial sums (double for accuracy).
    double s = 0.0;
    for (int t = threadIdx.x; t < TT; t += 256) {
        float v = ab[t];
        sa[t] = v;
        s += (double)v;
    }
    red[threadIdx.x] = s;
    __syncthreads();
    #pragma unroll
    for (int o = 128; o > 0; o >>= 1) {
        if (threadIdx.x < o) red[threadIdx.x] += red[threadIdx.x + o];
        __syncthreads();
    }

    if (threadIdx.x == 0) {
        const float scale = (float)tlen[b] / (float)red[0];
        g_scale[b] = scale;

        float integ = 0.0f;
        int   k     = 0;
        #pragma unroll 4
        for (int t = 0; t < TT; t++) {
            const float a    = sa[t] * scale;
            const float dist = 1.0f - integ;     // dist_completion (pre-add)
            integ += a;
            if (integ >= THRESH) {
                g_fire[b * LL + k] = t;
                g_cur [b * LL + k] = dist;       // cur = dist_completion at fire
                g_rem [b * LL + k] = a - dist;   // remainds = alpha - cur
                k++;
                integ -= 1.0f;
                if (k == LL) break;              // tokens >= L are dropped anyway
            }
        }
        g_ntok[b] = k;
    }
}

// ---------------------------------------------------------------------------
// Kernel 2: segmented weighted reduction of hidden -> out[b,k,:].
// Grid (L, B); 128 threads; each thread owns 4 contiguous channels (float4).
// Writes zeros for padded tokens (out is poisoned to 0xAA by the harness).
// ---------------------------------------------------------------------------
__global__ void cif_gather_kernel(const float* __restrict__ hidden,
                                  const float* __restrict__ alphas,
                                  float*       __restrict__ out)
{
    const int k   = blockIdx.x;
    const int b   = blockIdx.y;
    const int tid = threadIdx.x;            // 0..127, 4 floats each -> H=512

    float4 acc = make_float4(0.f, 0.f, 0.f, 0.f);

    const int ntok = g_ntok[b];
    if (k < ntok) {
        const int   t1     = g_fire[b * LL + k];
        const int   t0     = (k == 0) ? 0 : g_fire[b * LL + k - 1];
        const float wlast  = g_cur[b * LL + k];
        const float wfirst = (k == 0) ? 0.0f : g_rem[b * LL + k - 1];
        const float scale  = g_scale[b];
        const float* __restrict__ ap = alphas + (size_t)b * TT;

        const float4* __restrict__ hp =
            reinterpret_cast<const float4*>(hidden + ((size_t)b * TT + t0) * HH) + tid;

        for (int t = t0; t <= t1; t++) {
            float w;
            if (t == t1)                w = wlast;        // firing frame: dist_completion
            else if (k > 0 && t == t0)  w = wfirst;       // carry-in: remainds of prev fire
            else                        w = ap[t] * scale; // interior: scaled alpha
            const float4 h = *hp;
            hp += HH / 4;
            acc.x += w * h.x;
            acc.y += w * h.y;
            acc.z += w * h.z;
            acc.w += w * h.w;
        }
    }

    reinterpret_cast<float4*>(out + (size_t)(b * LL + k) * HH)[tid] = acc;
}

// ---------------------------------------------------------------------------
extern "C" void kernel_launch(void* const* d_in, const int* in_sizes, int n_in,
                              void* d_out, int out_size)
{
    const float* hidden = (const float*)d_in[0];   // [B,T,H]
    const float* alphas = (const float*)d_in[1];   // [B,T]
    const int*   tlen   = (const int*)  d_in[2];   // [B]
    float*       out    = (float*)d_out;           // [B,L,H]

    cif_scan_kernel<<<BB, 256>>>(alphas, tlen);

    dim3 grid(LL, BB);
    cif_gather_kernel<<<grid, 128>>>(hidden, alphas, out);
}

// round 2
// speedup vs baseline: 1.1774x; 1.1774x over previous
#include <cuda_runtime.h>

// CIF: continuous integrate-and-fire.
// hidden [B,T,H] f32, alphas [B,T] f32, target_lengths [B] i32 -> out [B,L,H] f32.
#define BB 32
#define TT 2000
#define HH 512
#define LL 256
#define THRESH 0.95f

// Scratch (no device allocation allowed -> __device__ globals).
__device__ int   g_fire[BB * LL];   // fire time per token
__device__ float g_cur [BB * LL];   // weight of the firing frame for this token
__device__ float g_rem [BB * LL];   // leftover weight of firing frame -> next token
__device__ float g_scale[BB];       // per-batch alpha rescale factor
__device__ int   g_ntok[BB];        // number of emitted tokens (<= LL)

// ---------------------------------------------------------------------------
// Kernel 1: per-batch alpha sum + exact sequential fire scan.
// One CTA per batch (each lands on its own SM). The scan replays the exact
// reference FP order; the loop-carried chain is FADD + FSETP/FSEL (~12 cyc).
// ---------------------------------------------------------------------------
__global__ void cif_scan_kernel(const float* __restrict__ alphas,
                                const int*   __restrict__ tlen)
{
    const int b = blockIdx.x;
    __shared__ float  sa[TT + 1];    // +1 so prefetch of t=TT is safe
    __shared__ double red[256];

    const float* ab = alphas + (size_t)b * TT;

    // Stage alphas into smem and accumulate partial sums (double for accuracy).
    double s = 0.0;
    for (int t = threadIdx.x; t < TT; t += 256) {
        float v = ab[t];
        sa[t] = v;
        s += (double)v;
    }
    if (threadIdx.x == 0) sa[TT] = 0.0f;
    red[threadIdx.x] = s;
    __syncthreads();
    #pragma unroll
    for (int o = 128; o > 0; o >>= 1) {
        if (threadIdx.x < o) red[threadIdx.x] += red[threadIdx.x + o];
        __syncthreads();
    }

    if (threadIdx.x == 0) {
        const float scale = (float)tlen[b] / (float)red[0];
        g_scale[b] = scale;

        int*   fOut = g_fire + b * LL;
        float* cOut = g_cur  + b * LL;
        float* rOut = g_rem  + b * LL;

        float integ  = 0.0f;
        int   k      = 0;
        // Prefetch one alpha ahead: LDS (29 cyc) + FMUL stay off the chain.
        float a      = sa[0] * scale;
        #pragma unroll 4
        for (int t = 0; t < TT; t++) {
            const float a_next = sa[t + 1] * scale;   // independent prefetch
            const float snew   = integ + a;           // FADD (4)
            const bool  fire   = (snew >= THRESH);    // FSETP (pred-as-data: 4)
            const float sm1    = snew - 1.0f;         // parallel FADD (exact, Sterbenz)
            integ = fire ? sm1 : snew;                // FSEL (4)  -> 12-cyc chain
            if (fire) {                               // rare (~10%), off-chain
                fOut[k] = t;
                cOut[k] = 1.0f - (snew - a);          // dist_completion = 1 - old integ
                rOut[k] = a - (1.0f - (snew - a));    // remainds = alpha - cur
                k++;
                if (k == LL) break;                   // tokens >= L are dropped
            }
            a = a_next;
        }
        g_ntok[b] = k;
    }
}

// ---------------------------------------------------------------------------
// Kernel 2: segmented weighted reduction of hidden -> out[b,k,:].
// Grid (L, B); 128 threads; each thread owns 4 contiguous channels (float4).
// Boundary frames peeled so the interior loop is branch-free and unrolls x4
// (front-batched LDG.128s -> MLP 4).
// ---------------------------------------------------------------------------
__global__ void cif_gather_kernel(const float* __restrict__ hidden,
                                  const float* __restrict__ alphas,
                                  float*       __restrict__ out)
{
    const int k   = blockIdx.x;
    const int b   = blockIdx.y;
    const int tid = threadIdx.x;            // 0..127, float4 each -> H=512

    float4 acc = make_float4(0.f, 0.f, 0.f, 0.f);

    const int ntok = g_ntok[b];
    if (k < ntok) {
        const int   t1    = g_fire[b * LL + k];
        const float wlast = g_cur [b * LL + k];
        const float scale = g_scale[b];
        const float* __restrict__ ap = alphas + (size_t)b * TT;
        const float4* __restrict__ hbase =
            reinterpret_cast<const float4*>(hidden + (size_t)b * TT * HH) + tid;

        int tstart;
        if (k == 0) {
            tstart = 0;
        } else {
            const int   t0     = g_fire[b * LL + k - 1];
            const float wfirst = g_rem [b * LL + k - 1];
            const float4 h0 = hbase[(size_t)t0 * (HH / 4)];
            acc.x = wfirst * h0.x; acc.y = wfirst * h0.y;
            acc.z = wfirst * h0.z; acc.w = wfirst * h0.w;
            tstart = t0 + 1;
        }

        // Interior frames: weight = scaled alpha. Branch-free, unrolled.
        #pragma unroll 4
        for (int t = tstart; t < t1; t++) {
            const float  w = ap[t] * scale;
            const float4 h = hbase[(size_t)t * (HH / 4)];
            acc.x += w * h.x; acc.y += w * h.y;
            acc.z += w * h.z; acc.w += w * h.w;
        }

        // Firing frame: weight = dist_completion.
        {
            const float4 h = hbase[(size_t)t1 * (HH / 4)];
            acc.x += wlast * h.x; acc.y += wlast * h.y;
            acc.z += wlast * h.z; acc.w += wlast * h.w;
        }
    }

    reinterpret_cast<float4*>(out + (size_t)(b * LL + k) * HH)[tid] = acc;
}

// ---------------------------------------------------------------------------
extern "C" void kernel_launch(void* const* d_in, const int* in_sizes, int n_in,
                              void* d_out, int out_size)
{
    const float* hidden = (const float*)d_in[0];   // [B,T,H]
    const float* alphas = (const float*)d_in[1];   // [B,T]
    const int*   tlen   = (const int*)  d_in[2];   // [B]
    float*       out    = (float*)d_out;           // [B,L,H]

    cif_scan_kernel<<<BB, 256>>>(alphas, tlen);

    dim3 grid(LL, BB);
    cif_gather_kernel<<<grid, 128>>>(hidden, alphas, out);
}